// round 4
// baseline (speedup 1.0000x reference)
#include <cuda_runtime.h>
#include <cstdint>

// Problem constants
#define MB 8192      // B*S
#define HH 1024      // H
#define RR 2048      // R (= L)
#define SS 2048
#define BB 4
#define NCH 64       // scan chunks
#define CH  32       // steps per chunk

// scratch: 6 slabs [MB,RR] + 3 chunk arrays
__device__ float g_scratch[6ull * MB * RR + 3ull * BB * NCH * RR];

// ---------------------------------------------------------------------------
// TF32 mma.sync GEMM: CTA tile 128x256, BK=16, 8 warps @ 64x64 warp tiles.
// smem rows of 16 floats with float4-block XOR swizzle (conflict-free,
// validated in R2). Double-buffered, STS interleaved between k8 MMA groups.
// ---------------------------------------------------------------------------
#define BM 128
#define BN 256
#define BK 16
#define A_FLOATS (BM * BK)            // 2048
#define B_FLOATS (BN * BK)            // 4096
#define STAGE_FLOATS (A_FLOATS + B_FLOATS)   // 6144 (24KB)
#define SMEM_DYN (2 * STAGE_FLOATS * 4)      // 49152

__device__ __forceinline__ float to_tf32(float x) {
    unsigned u;
    asm("cvt.rna.tf32.f32 %0, %1;" : "=r"(u) : "f"(x));
    return __uint_as_float(u);
}

__device__ __forceinline__ void mma_tf32(float c[4], const float a[4], const float b[2]) {
    asm volatile(
        "mma.sync.aligned.m16n8k8.row.col.f32.tf32.tf32.f32 "
        "{%0,%1,%2,%3}, {%4,%5,%6,%7}, {%8,%9}, {%0,%1,%2,%3};"
        : "+f"(c[0]), "+f"(c[1]), "+f"(c[2]), "+f"(c[3])
        : "r"(__float_as_uint(a[0])), "r"(__float_as_uint(a[1])),
          "r"(__float_as_uint(a[2])), "r"(__float_as_uint(a[3])),
          "r"(__float_as_uint(b[0])), "r"(__float_as_uint(b[1])));
}

// swizzled float index into a [rows][16] tile
__device__ __forceinline__ int swz16(int row, int col) {
    int blk = (col >> 2) ^ ((row >> 1) & 3);
    return row * 16 + (blk << 2) + (col & 3);
}

__device__ __forceinline__ float act_apply(float x, int act) {
    if (act == 1) return tanhf(x);
    if (act == 2) return 1.0f / (1.0f + __expf(-x));
    if (act == 3) return x / (1.0f + __expf(-x));
    return x;
}

// Core K-loop: acc += A[bm:+128, :K] @ W[bn:+256, :K]^T
// A2 != null -> A elementwise-multiplied by A2 (fused up*gate).
__device__ __forceinline__ void gemm_core(
    const float* __restrict__ A, const float* __restrict__ A2,
    const float* __restrict__ W, int K, int bm, int bn,
    float* __restrict__ smem, int tid, float acc[4][8][4])
{
    const int lane = tid & 31;
    const int wid  = tid >> 5;
    const int wm   = (wid >> 2) * 64;   // 0 or 64
    const int wn   = (wid & 3) * 64;    // 0,64,128,192
    const int fr   = lane >> 2;         // 0..7
    const int fc   = lane & 3;          // 0..3

    const int nk = K >> 4;
    float4 va[2], vb[4];

#define LDG_TILE(k0)                                                                \
    {                                                                               \
        _Pragma("unroll")                                                           \
        for (int i = 0; i < 2; ++i) {                                               \
            const int id = tid + (i << 8);                                          \
            const int row = id >> 2, c4 = id & 3;                                   \
            va[i] = *(const float4*)(A + (size_t)(bm + row) * K + (k0) + (c4 << 2)); \
            if (A2) {                                                               \
                const float4 m = *(const float4*)(A2 + (size_t)(bm + row) * K + (k0) + (c4 << 2)); \
                va[i].x *= m.x; va[i].y *= m.y; va[i].z *= m.z; va[i].w *= m.w;     \
            }                                                                       \
        }                                                                           \
        _Pragma("unroll")                                                           \
        for (int i = 0; i < 4; ++i) {                                               \
            const int id = tid + (i << 8);                                          \
            const int row = id >> 2, c4 = id & 3;                                   \
            vb[i] = *(const float4*)(W + (size_t)(bn + row) * K + (k0) + (c4 << 2)); \
        }                                                                           \
    }

#define STS_TILE(buf)                                                               \
    {                                                                               \
        float* As_ = smem + (buf) * STAGE_FLOATS;                                   \
        float* Bs_ = As_ + A_FLOATS;                                                \
        _Pragma("unroll")                                                           \
        for (int i = 0; i < 2; ++i) {                                               \
            const int id = tid + (i << 8);                                          \
            const int row = id >> 2, c4 = id & 3;                                   \
            const int pb = c4 ^ ((row >> 1) & 3);                                   \
            float4 t;                                                               \
            t.x = to_tf32(va[i].x); t.y = to_tf32(va[i].y);                         \
            t.z = to_tf32(va[i].z); t.w = to_tf32(va[i].w);                         \
            *(float4*)(As_ + row * 16 + (pb << 2)) = t;                             \
        }                                                                           \
        _Pragma("unroll")                                                           \
        for (int i = 0; i < 4; ++i) {                                               \
            const int id = tid + (i << 8);                                          \
            const int row = id >> 2, c4 = id & 3;                                   \
            const int pb = c4 ^ ((row >> 1) & 3);                                   \
            float4 t;                                                               \
            t.x = to_tf32(vb[i].x); t.y = to_tf32(vb[i].y);                         \
            t.z = to_tf32(vb[i].z); t.w = to_tf32(vb[i].w);                         \
            *(float4*)(Bs_ + row * 16 + (pb << 2)) = t;                             \
        }                                                                           \
    }

#define FRAG_MMA(kb, As_, Bs_)                                                      \
    {                                                                               \
        float af[4][4];                                                             \
        _Pragma("unroll")                                                           \
        for (int ms = 0; ms < 4; ++ms) {                                            \
            const int r0 = wm + ms * 16 + fr;                                       \
            af[ms][0] = (As_)[swz16(r0,     (kb) + fc)];                            \
            af[ms][1] = (As_)[swz16(r0 + 8, (kb) + fc)];                            \
            af[ms][2] = (As_)[swz16(r0,     (kb) + fc + 4)];                        \
            af[ms][3] = (As_)[swz16(r0 + 8, (kb) + fc + 4)];                        \
        }                                                                           \
        float bf[8][2];                                                             \
        _Pragma("unroll")                                                           \
        for (int ns = 0; ns < 8; ++ns) {                                            \
            const int n0 = wn + ns * 8 + fr;                                        \
            bf[ns][0] = (Bs_)[swz16(n0, (kb) + fc)];                                \
            bf[ns][1] = (Bs_)[swz16(n0, (kb) + fc + 4)];                            \
        }                                                                           \
        _Pragma("unroll")                                                           \
        for (int ms = 0; ms < 4; ++ms)                                              \
            _Pragma("unroll")                                                       \
            for (int ns = 0; ns < 8; ++ns)                                          \
                mma_tf32(acc[ms][ns], af[ms], bf[ns]);                              \
    }

    // preload stage 0
    LDG_TILE(0);
    STS_TILE(0);
    __syncthreads();

    for (int kt = 0; kt < nk; ++kt) {
        const int buf = kt & 1;
        float* As = smem + buf * STAGE_FLOATS;
        float* Bs = As + A_FLOATS;

        const bool more = (kt + 1 < nk);
        if (more) LDG_TILE((kt + 1) << 4);

        FRAG_MMA(0, As, Bs);            // k8 group 0

        if (more) STS_TILE(buf ^ 1);    // stage next tile between MMA groups

        FRAG_MMA(8, As, Bs);            // k8 group 1

        __syncthreads();
    }
#undef LDG_TILE
#undef STS_TILE
#undef FRAG_MMA
}

__device__ __forceinline__ void epilogue(
    float* __restrict__ O, int ldn, int bm, int bn, int tid,
    float acc[4][8][4], int act)
{
    const int lane = tid & 31;
    const int wid  = tid >> 5;
    const int wm   = (wid >> 2) * 64;
    const int wn   = (wid & 3) * 64;
    const int fr   = lane >> 2;
    const int fc   = lane & 3;

#pragma unroll
    for (int ms = 0; ms < 4; ++ms) {
#pragma unroll
        for (int ns = 0; ns < 8; ++ns) {
            const int m0 = bm + wm + ms * 16 + fr;
            const int n0 = bn + wn + ns * 8 + 2 * fc;
            float2 v0, v1;
            v0.x = act_apply(acc[ms][ns][0], act);
            v0.y = act_apply(acc[ms][ns][1], act);
            v1.x = act_apply(acc[ms][ns][2], act);
            v1.y = act_apply(acc[ms][ns][3], act);
            *(float2*)&O[(size_t)m0 * ldn + n0] = v0;
            *(float2*)&O[(size_t)(m0 + 8) * ldn + n0] = v1;
        }
    }
}

// Fused 6-projection kernel: grid (M/128=64, RR/256=8, 6 weights)
__global__ __launch_bounds__(256)
void proj_tc(const float* __restrict__ x,
             const float* __restrict__ W0, const float* __restrict__ W1,
             const float* __restrict__ W2, const float* __restrict__ W3,
             const float* __restrict__ W4, const float* __restrict__ W5,
             float* o0, float* o1, float* o2, float* o3, float* o4, float* o5)
{
    extern __shared__ float smem[];
    const int tid = threadIdx.x;
    const int bm = blockIdx.x * BM;
    const int bn = blockIdx.y * BN;

    const float* W; float* O; int act;
    switch (blockIdx.z) {
        case 0:  W = W0; O = o0; act = 1; break;   // forget: tanh
        case 1:  W = W1; O = o1; act = 2; break;   // input: sigmoid
        case 2:  W = W2; O = o2; act = 3; break;   // value: silu
        case 3:  W = W3; O = o3; act = 0; break;   // query
        case 4:  W = W4; O = o4; act = 0; break;   // up
        default: W = W5; O = o5; act = 3; break;   // gate: silu
    }

    float acc[4][8][4];
#pragma unroll
    for (int i = 0; i < 4; ++i)
#pragma unroll
        for (int j = 0; j < 8; ++j)
#pragma unroll
            for (int k = 0; k < 4; ++k) acc[i][j][k] = 0.0f;

    gemm_core(x, nullptr, W, HH, bm, bn, smem, tid, acc);
    epilogue(O, RR, bm, bn, tid, acc, act);
}

// Fused output: out = RO @ Wro^T + (up*gate) @ Wd^T.  grid (64, HH/256=4)
__global__ __launch_bounds__(256)
void out_tc(const float* __restrict__ ro, const float* __restrict__ Wro,
            const float* __restrict__ up, const float* __restrict__ gt,
            const float* __restrict__ Wd, float* __restrict__ O)
{
    extern __shared__ float smem[];
    const int tid = threadIdx.x;
    const int bm = blockIdx.x * BM;
    const int bn = blockIdx.y * BN;

    float acc[4][8][4];
#pragma unroll
    for (int i = 0; i < 4; ++i)
#pragma unroll
        for (int j = 0; j < 8; ++j)
#pragma unroll
            for (int k = 0; k < 4; ++k) acc[i][j][k] = 0.0f;

    gemm_core(ro, nullptr, Wro, RR, bm, bn, smem, tid, acc);
    __syncthreads();
    gemm_core(up, gt,      Wd,  RR, bm, bn, smem, tid, acc);
    epilogue(O, HH, bm, bn, tid, acc, 0);
}

// ---------------------------------------------------------------------------
// Chunked parallel scan (NCH=64 chunks of 32 steps)
// ---------------------------------------------------------------------------
__global__ void scan_p1(const float* __restrict__ F, const float* __restrict__ G,
                        const float* __restrict__ C,
                        float* __restrict__ chA, float* __restrict__ chY)
{
    const int t  = blockIdx.x * blockDim.x + threadIdx.x;
    const int r  = t & (RR - 1);
    const int bc = t >> 11;
    const int ch = bc & (NCH - 1);
    const int b  = bc >> 6;

    const size_t base = ((size_t)b * SS + (size_t)ch * CH) * RR + r;
    float a = 1.0f, y = 0.0f;
#pragma unroll 8
    for (int s = 0; s < CH; ++s) {
        const size_t idx = base + (size_t)s * RR;
        const float f  = F[idx];
        const float gc = G[idx] * C[idx];
        y = fmaf(f, y, gc);
        a *= f;
    }
    const int o = (b * NCH + ch) * RR + r;
    chA[o] = a;
    chY[o] = y;
}

__global__ void scan_p2(const float* __restrict__ chA, const float* __restrict__ chY,
                        const float* __restrict__ s0, float* __restrict__ carry)
{
    const int t = blockIdx.x * blockDim.x + threadIdx.x;
    const int r = t & (RR - 1);
    const int b = t >> 11;

    float c = s0[r];
#pragma unroll
    for (int ch = 0; ch < NCH; ++ch) {
        const int o = (b * NCH + ch) * RR + r;
        carry[o] = c;
        c = fmaf(chA[o], c, chY[o]);
    }
}

__global__ void scan_p3(const float* __restrict__ F, const float* __restrict__ G,
                        const float* __restrict__ C, const float* __restrict__ Q,
                        const float* __restrict__ carry, float* __restrict__ RO)
{
    const int t  = blockIdx.x * blockDim.x + threadIdx.x;
    const int r  = t & (RR - 1);
    const int bc = t >> 11;
    const int ch = bc & (NCH - 1);
    const int b  = bc >> 6;

    const size_t base = ((size_t)b * SS + (size_t)ch * CH) * RR + r;
    float state = carry[(b * NCH + ch) * RR + r];
#pragma unroll 8
    for (int s = 0; s < CH; ++s) {
        const size_t idx = base + (size_t)s * RR;
        const float f  = F[idx];
        const float gc = G[idx] * C[idx];
        state = fmaf(f, state, gc);
        const float xq = Q[idx] * state;
        RO[idx] = xq / (1.0f + __expf(-xq));
    }
}

// ---------------------------------------------------------------------------
extern "C" void kernel_launch(void* const* d_in, const int* in_sizes, int n_in,
                              void* d_out, int out_size)
{
    const float* x   = (const float*)d_in[0];
    const float* Wf  = (const float*)d_in[1];
    const float* Wi  = (const float*)d_in[2];
    const float* Wv  = (const float*)d_in[3];
    const float* Wq  = (const float*)d_in[4];
    const float* Wro = (const float*)d_in[5];
    const float* Wu  = (const float*)d_in[6];
    const float* Wg  = (const float*)d_in[7];
    const float* Wd  = (const float*)d_in[8];
    const float* s0  = (const float*)d_in[9];
    float* out = (float*)d_out;

    float* scr = nullptr;
    cudaGetSymbolAddress((void**)&scr, g_scratch);
    float* f   = scr + 0ull * MB * RR;
    float* g   = scr + 1ull * MB * RR;
    float* c   = scr + 2ull * MB * RR;
    float* q   = scr + 3ull * MB * RR;   // readout written in-place
    float* up  = scr + 4ull * MB * RR;
    float* gt  = scr + 5ull * MB * RR;
    float* chA = scr + 6ull * MB * RR;
    float* chY = chA + (size_t)BB * NCH * RR;
    float* car = chY + (size_t)BB * NCH * RR;

    cudaFuncSetAttribute(proj_tc, cudaFuncAttributeMaxDynamicSharedMemorySize, SMEM_DYN);
    cudaFuncSetAttribute(out_tc,  cudaFuncAttributeMaxDynamicSharedMemorySize, SMEM_DYN);

    // 1. six projections; x-tile index fastest so weights stay L2-hot
    proj_tc<<<dim3(MB / BM, RR / BN, 6), 256, SMEM_DYN>>>(
        x, Wf, Wi, Wv, Wq, Wu, Wg, f, g, c, q, up, gt);

    // 2. chunked scan + fused readout
    scan_p1<<<(BB * NCH * RR) / 256, 256>>>(f, g, c, chA, chY);
    scan_p2<<<(BB * RR) / 256, 256>>>(chA, chY, s0, car);
    scan_p3<<<(BB * NCH * RR) / 256, 256>>>(f, g, c, q, car, q);

    // 3. out = RO @ Wro^T + (up*gate) @ Wd^T  (up*gate fused in loader)
    out_tc<<<dim3(MB / BM, HH / BN, 1), 256, SMEM_DYN>>>(q, Wro, up, gt, Wd, out);
}

// round 5
// speedup vs baseline: 2.2631x; 2.2631x over previous
#include <cuda_runtime.h>
#include <cuda_fp16.h>
#include <cstdint>

// Problem constants
#define MB 8192      // B*S
#define HH 1024      // H
#define RR 2048      // R (= L)
#define SS 2048
#define BB 4
#define NCH 64       // scan chunks
#define CH  32       // steps per chunk

// fp32 scratch: f,g,c,q,up,gt slabs + scan chunk arrays
__device__ float g_scratch[6ull * MB * RR + 3ull * BB * NCH * RR];
// fp16 scratch: x_h | w_h(6 proj weights) | wrod_h(HHx4096) | rohp_h(MBx4096)
#define XH_OFF   0ull
#define WH_OFF   ((size_t)MB * HH)
#define WROD_OFF (WH_OFF + 6ull * RR * HH)
#define ROHP_OFF (WROD_OFF + (size_t)HH * 2 * RR)
__device__ __half g_half[ROHP_OFF + (size_t)MB * 2 * RR];

// ---------------------------------------------------------------------------
// fp16 mma.sync m16n8k16 GEMM.  CTA 128x128, BK=32, 8 warps @ 64x32.
// smem rows: 32 halves (64B) = 4 16B chunks; swizzle chunk' = chunk ^ f(row),
// f(row) = (row&3) ^ ((row>>2)&1)  -> conflict-free STS and fragment LDS.
// ---------------------------------------------------------------------------
#define BM 128
#define BN 128
#define BK 32
#define TILE_HALVES (128 * 32)        // 4096 halves = 8KB per operand stage

__device__ __forceinline__ int f_row(int row) { return (row & 3) ^ ((row >> 2) & 1); }
// half-index into a [128][32] tile; pc = b32 column 0..7
__device__ __forceinline__ int sw_idx(int row, int pc) {
    return (row << 5) + ((((pc >> 2) ^ f_row(row)) & 3) << 3) + ((pc & 3) << 1);
}

__device__ __forceinline__ void mma_f16(float c[4], const uint32_t a[4], const uint32_t b[2]) {
    asm volatile(
        "mma.sync.aligned.m16n8k16.row.col.f32.f16.f16.f32 "
        "{%0,%1,%2,%3}, {%4,%5,%6,%7}, {%8,%9}, {%0,%1,%2,%3};"
        : "+f"(c[0]), "+f"(c[1]), "+f"(c[2]), "+f"(c[3])
        : "r"(a[0]), "r"(a[1]), "r"(a[2]), "r"(a[3]), "r"(b[0]), "r"(b[1]));
}

__device__ __forceinline__ float act_apply(float x, int act) {
    if (act == 1) return tanhf(x);
    if (act == 2) return 1.0f / (1.0f + __expf(-x));
    if (act == 3) return x / (1.0f + __expf(-x));
    return x;
}

// acc += A[bm:+128, :K] @ W[bn:+128, :K]^T   (A, W fp16, row-major, ld = K)
__device__ __forceinline__ void gemm_core(
    const __half* __restrict__ A, const __half* __restrict__ W, int K,
    int bm, int bn, __half* smA, __half* smB, int tid, float acc[4][4][4])
{
    const int lane = tid & 31;
    const int wid  = tid >> 5;
    const int wm   = (wid >> 2) * 64;   // 0 or 64
    const int wn   = (wid & 3) * 32;    // 0,32,64,96
    const int fr   = lane >> 2;         // 0..7
    const int fc   = lane & 3;          // 0..3

    const int nk = K >> 5;              // k-tiles of 32

    // loader: 2 chunks (16B) per operand per thread. cid = tid + 256*i
    uint4 sa[2], sb[2];

#define LDG_TILE(k0)                                                            \
    {                                                                           \
        _Pragma("unroll")                                                       \
        for (int i = 0; i < 2; ++i) {                                           \
            const int cid = tid + (i << 8);                                     \
            const int row = cid >> 2, ch = cid & 3;                             \
            sa[i] = *(const uint4*)(A + (size_t)(bm + row) * K + (k0) + (ch << 3)); \
            sb[i] = *(const uint4*)(W + (size_t)(bn + row) * K + (k0) + (ch << 3)); \
        }                                                                       \
    }

#define STS_TILE(buf)                                                           \
    {                                                                           \
        __half* a_ = smA + (buf) * TILE_HALVES;                                 \
        __half* b_ = smB + (buf) * TILE_HALVES;                                 \
        _Pragma("unroll")                                                       \
        for (int i = 0; i < 2; ++i) {                                           \
            const int cid = tid + (i << 8);                                     \
            const int row = cid >> 2, ch = cid & 3;                             \
            const int chs = ch ^ f_row(row);                                    \
            *(uint4*)(a_ + (row << 5) + (chs << 3)) = sa[i];                    \
            *(uint4*)(b_ + (row << 5) + (chs << 3)) = sb[i];                    \
        }                                                                       \
    }

#define FRAG_MMA(g, a_, b_)                                                     \
    {                                                                           \
        uint32_t af[4][4];                                                      \
        _Pragma("unroll")                                                       \
        for (int ms = 0; ms < 4; ++ms) {                                        \
            const int r0 = wm + ms * 16 + fr;                                   \
            af[ms][0] = *(const uint32_t*)((a_) + sw_idx(r0,     8*(g) + fc));      \
            af[ms][1] = *(const uint32_t*)((a_) + sw_idx(r0 + 8, 8*(g) + fc));      \
            af[ms][2] = *(const uint32_t*)((a_) + sw_idx(r0,     8*(g) + 4 + fc));  \
            af[ms][3] = *(const uint32_t*)((a_) + sw_idx(r0 + 8, 8*(g) + 4 + fc));  \
        }                                                                       \
        uint32_t bf[4][2];                                                      \
        _Pragma("unroll")                                                       \
        for (int ns = 0; ns < 4; ++ns) {                                        \
            const int n0 = wn + ns * 8 + fr;                                    \
            bf[ns][0] = *(const uint32_t*)((b_) + sw_idx(n0, 8*(g) + fc));          \
            bf[ns][1] = *(const uint32_t*)((b_) + sw_idx(n0, 8*(g) + 4 + fc));      \
        }                                                                       \
        _Pragma("unroll")                                                       \
        for (int ms = 0; ms < 4; ++ms)                                          \
            _Pragma("unroll")                                                   \
            for (int ns = 0; ns < 4; ++ns)                                      \
                mma_f16(acc[ms][ns], af[ms], bf[ns]);                           \
    }

    LDG_TILE(0);
    STS_TILE(0);
    __syncthreads();

    for (int kt = 0; kt < nk; ++kt) {
        const int buf = kt & 1;
        __half* a_ = smA + buf * TILE_HALVES;
        __half* b_ = smB + buf * TILE_HALVES;

        const bool more = (kt + 1 < nk);
        if (more) LDG_TILE((kt + 1) << 5);

        FRAG_MMA(0, a_, b_);
        FRAG_MMA(1, a_, b_);

        if (more) STS_TILE(buf ^ 1);
        __syncthreads();
    }
#undef LDG_TILE
#undef STS_TILE
#undef FRAG_MMA
}

__device__ __forceinline__ void epilogue(
    float* __restrict__ O, int ldn, int bm, int bn, int tid,
    float acc[4][4][4], int act)
{
    const int lane = tid & 31;
    const int wid  = tid >> 5;
    const int wm   = (wid >> 2) * 64;
    const int wn   = (wid & 3) * 32;
    const int fr   = lane >> 2;
    const int fc   = lane & 3;

#pragma unroll
    for (int ms = 0; ms < 4; ++ms) {
#pragma unroll
        for (int ns = 0; ns < 4; ++ns) {
            const int m0 = bm + wm + ms * 16 + fr;
            const int n0 = bn + wn + ns * 8 + 2 * fc;
            float2 v0, v1;
            v0.x = act_apply(acc[ms][ns][0], act);
            v0.y = act_apply(acc[ms][ns][1], act);
            v1.x = act_apply(acc[ms][ns][2], act);
            v1.y = act_apply(acc[ms][ns][3], act);
            *(float2*)&O[(size_t)m0 * ldn + n0] = v0;
            *(float2*)&O[(size_t)(m0 + 8) * ldn + n0] = v1;
        }
    }
}

// Fused 6-projection: grid (M/128=64, RR/128=16, 6)
__global__ __launch_bounds__(256, 2)
void proj_tc(const __half* __restrict__ xh, const __half* __restrict__ wh,
             float* o0, float* o1, float* o2, float* o3, float* o4, float* o5)
{
    __shared__ __half smA[2 * TILE_HALVES];
    __shared__ __half smB[2 * TILE_HALVES];

    const int tid = threadIdx.x;
    const int bm = blockIdx.x * BM;
    const int bn = blockIdx.y * BN;

    const __half* W = wh + (size_t)blockIdx.z * RR * HH;
    float* O; int act;
    switch (blockIdx.z) {
        case 0:  O = o0; act = 1; break;   // forget: tanh
        case 1:  O = o1; act = 2; break;   // input: sigmoid
        case 2:  O = o2; act = 3; break;   // value: silu
        case 3:  O = o3; act = 0; break;   // query
        case 4:  O = o4; act = 0; break;   // up
        default: O = o5; act = 3; break;   // gate: silu
    }

    float acc[4][4][4];
#pragma unroll
    for (int i = 0; i < 4; ++i)
#pragma unroll
        for (int j = 0; j < 4; ++j)
#pragma unroll
            for (int k = 0; k < 4; ++k) acc[i][j][k] = 0.0f;

    gemm_core(xh, W, HH, bm, bn, smA, smB, tid, acc);
    epilogue(O, RR, bm, bn, tid, acc, act);
}

// Output GEMM: out[MB,HH] = rohp[MB,4096] @ wrod[HH,4096]^T.  grid (64, 8)
__global__ __launch_bounds__(256, 2)
void out_tc(const __half* __restrict__ rohp, const __half* __restrict__ wrod,
            float* __restrict__ O)
{
    __shared__ __half smA[2 * TILE_HALVES];
    __shared__ __half smB[2 * TILE_HALVES];

    const int tid = threadIdx.x;
    const int bm = blockIdx.x * BM;
    const int bn = blockIdx.y * BN;

    float acc[4][4][4];
#pragma unroll
    for (int i = 0; i < 4; ++i)
#pragma unroll
        for (int j = 0; j < 4; ++j)
#pragma unroll
            for (int k = 0; k < 4; ++k) acc[i][j][k] = 0.0f;

    gemm_core(rohp, wrod, 2 * RR, bm, bn, smA, smB, tid, acc);
    epilogue(O, HH, bm, bn, tid, acc, 0);
}

// ---------------------------------------------------------------------------
// fp32 -> fp16 conversion kernels
// ---------------------------------------------------------------------------
__global__ void cvt_x(const float* __restrict__ src, __half* __restrict__ dst, int n4)
{
    const int i = blockIdx.x * blockDim.x + threadIdx.x;
    if (i < n4) {
        const float4 v = ((const float4*)src)[i];
        __half2 h0 = __floats2half2_rn(v.x, v.y);
        __half2 h1 = __floats2half2_rn(v.z, v.w);
        ((__half2*)dst)[2 * i]     = h0;
        ((__half2*)dst)[2 * i + 1] = h1;
    }
}

// weights: blockIdx.y = 0..7. 0-5 -> w_h slabs; 6: Wro -> wrod[:, 0:2048];
// 7: Wd -> wrod[:, 2048:4096]. Each weight = RR*HH = 2M elems = 512K float4.
__global__ void cvt_w(const float* __restrict__ W0, const float* __restrict__ W1,
                      const float* __restrict__ W2, const float* __restrict__ W3,
                      const float* __restrict__ W4, const float* __restrict__ W5,
                      const float* __restrict__ Wro, const float* __restrict__ Wd,
                      __half* __restrict__ wh, __half* __restrict__ wrod)
{
    const int z = blockIdx.y;
    const int i = blockIdx.x * blockDim.x + threadIdx.x;   // float4 index, < 512K
    const float* src;
    switch (z) {
        case 0: src = W0; break; case 1: src = W1; break;
        case 2: src = W2; break; case 3: src = W3; break;
        case 4: src = W4; break; case 5: src = W5; break;
        case 6: src = Wro; break; default: src = Wd; break;
    }
    const float4 v = ((const float4*)src)[i];
    __half2 h0 = __floats2half2_rn(v.x, v.y);
    __half2 h1 = __floats2half2_rn(v.z, v.w);

    size_t di;
    if (z < 6) {
        di = (size_t)z * RR * HH + (size_t)i * 4;
    } else {
        const int row = i >> 9;             // / (RR/4 = 512)
        const int c4  = i & 511;
        di = (size_t)row * (2 * RR) + (z == 7 ? RR : 0) + (size_t)c4 * 4;
    }
    *(__half2*)(wrod ? (z < 6 ? wh + di : wrod + di) : wh) = h0;   // placeholder avoided below
    // (rewritten without ambiguity:)
    __half* d = (z < 6) ? (wh + di) : (wrod + di);
    *(__half2*)d = h0;
    *(__half2*)(d + 2) = h1;
}

// ---------------------------------------------------------------------------
// Chunked parallel scan
// ---------------------------------------------------------------------------
__global__ void scan_p1(const float* __restrict__ F, const float* __restrict__ G,
                        const float* __restrict__ C,
                        float* __restrict__ chA, float* __restrict__ chY)
{
    const int t  = blockIdx.x * blockDim.x + threadIdx.x;
    const int r  = t & (RR - 1);
    const int bc = t >> 11;
    const int ch = bc & (NCH - 1);
    const int b  = bc >> 6;

    const size_t base = ((size_t)b * SS + (size_t)ch * CH) * RR + r;
    float a = 1.0f, y = 0.0f;
#pragma unroll 8
    for (int s = 0; s < CH; ++s) {
        const size_t idx = base + (size_t)s * RR;
        const float f  = F[idx];
        const float gc = G[idx] * C[idx];
        y = fmaf(f, y, gc);
        a *= f;
    }
    const int o = (b * NCH + ch) * RR + r;
    chA[o] = a;
    chY[o] = y;
}

__global__ void scan_p2(const float* __restrict__ chA, const float* __restrict__ chY,
                        const float* __restrict__ s0, float* __restrict__ carry)
{
    const int t = blockIdx.x * blockDim.x + threadIdx.x;
    const int r = t & (RR - 1);
    const int b = t >> 11;

    float c = s0[r];
#pragma unroll
    for (int ch = 0; ch < NCH; ++ch) {
        const int o = (b * NCH + ch) * RR + r;
        carry[o] = c;
        c = fmaf(chA[o], c, chY[o]);
    }
}

// phase 3: recompute states, write RO = silu(q*state) as fp16 into rohp[:, 0:2048]
__global__ void scan_p3(const float* __restrict__ F, const float* __restrict__ G,
                        const float* __restrict__ C, const float* __restrict__ Q,
                        const float* __restrict__ carry, __half* __restrict__ rohp)
{
    const int t  = blockIdx.x * blockDim.x + threadIdx.x;
    const int r  = t & (RR - 1);
    const int bc = t >> 11;
    const int ch = bc & (NCH - 1);
    const int b  = bc >> 6;

    const size_t base = ((size_t)b * SS + (size_t)ch * CH) * RR + r;
    const size_t mrow0 = (size_t)b * SS + (size_t)ch * CH;
    float state = carry[(b * NCH + ch) * RR + r];
#pragma unroll 8
    for (int s = 0; s < CH; ++s) {
        const size_t idx = base + (size_t)s * RR;
        const float f  = F[idx];
        const float gc = G[idx] * C[idx];
        state = fmaf(f, state, gc);
        const float xq = Q[idx] * state;
        rohp[(mrow0 + s) * (2 * RR) + r] = __float2half(xq / (1.0f + __expf(-xq)));
    }
}

// hp = up * gate (gate already silu'd) -> fp16 into rohp[:, 2048:4096]
__global__ void mul_h(const float* __restrict__ up, const float* __restrict__ gate,
                      __half* __restrict__ rohp, int n4)
{
    const int i = blockIdx.x * blockDim.x + threadIdx.x;
    if (i < n4) {
        const float4 u = ((const float4*)up)[i];
        const float4 g = ((const float4*)gate)[i];
        __half2 h0 = __floats2half2_rn(u.x * g.x, u.y * g.y);
        __half2 h1 = __floats2half2_rn(u.z * g.z, u.w * g.w);
        const int row = i >> 9;             // / (RR/4)
        const int c4  = i & 511;
        __half* d = rohp + (size_t)row * (2 * RR) + RR + (size_t)c4 * 4;
        *(__half2*)d = h0;
        *(__half2*)(d + 2) = h1;
    }
}

// ---------------------------------------------------------------------------
extern "C" void kernel_launch(void* const* d_in, const int* in_sizes, int n_in,
                              void* d_out, int out_size)
{
    const float* x   = (const float*)d_in[0];
    const float* Wf  = (const float*)d_in[1];
    const float* Wi  = (const float*)d_in[2];
    const float* Wv  = (const float*)d_in[3];
    const float* Wq  = (const float*)d_in[4];
    const float* Wro = (const float*)d_in[5];
    const float* Wu  = (const float*)d_in[6];
    const float* Wg  = (const float*)d_in[7];
    const float* Wd  = (const float*)d_in[8];
    const float* s0  = (const float*)d_in[9];
    float* out = (float*)d_out;

    float* scr = nullptr;
    cudaGetSymbolAddress((void**)&scr, g_scratch);
    __half* hscr = nullptr;
    cudaGetSymbolAddress((void**)&hscr, g_half);

    float* f   = scr + 0ull * MB * RR;
    float* g   = scr + 1ull * MB * RR;
    float* c   = scr + 2ull * MB * RR;
    float* q   = scr + 3ull * MB * RR;
    float* up  = scr + 4ull * MB * RR;
    float* gt  = scr + 5ull * MB * RR;
    float* chA = scr + 6ull * MB * RR;
    float* chY = chA + (size_t)BB * NCH * RR;
    float* car = chY + (size_t)BB * NCH * RR;

    __half* xh   = hscr + XH_OFF;
    __half* wh   = hscr + WH_OFF;
    __half* wrod = hscr + WROD_OFF;
    __half* rohp = hscr + ROHP_OFF;

    // 0. fp32 -> fp16 conversions
    cvt_x<<<(MB * HH / 4) / 256, 256>>>(x, xh, MB * HH / 4);
    cvt_w<<<dim3((RR * HH / 4) / 256, 8), 256>>>(Wf, Wi, Wv, Wq, Wu, Wg, Wro, Wd, wh, wrod);

    // 1. six projections (fp16 tensor cores)
    proj_tc<<<dim3(MB / BM, RR / BN, 6), 256>>>(xh, wh, f, g, c, q, up, gt);

    // 2. chunked scan; p3 writes RO fp16 into rohp[:, 0:2048]
    scan_p1<<<(BB * NCH * RR) / 256, 256>>>(f, g, c, chA, chY);
    scan_p2<<<(BB * RR) / 256, 256>>>(chA, chY, s0, car);
    scan_p3<<<(BB * NCH * RR) / 256, 256>>>(f, g, c, q, car, rohp);

    // 3. hp = up*gate fp16 into rohp[:, 2048:4096]
    mul_h<<<(MB * RR / 4) / 256, 256>>>(up, gt, rohp, MB * RR / 4);

    // 4. out = rohp @ wrod^T  (K = 4096, covers rec + local in one GEMM)
    out_tc<<<dim3(MB / BM, HH / BN), 256>>>(rohp, wrod, out);
}

// round 6
// speedup vs baseline: 2.6856x; 1.1867x over previous
#include <cuda_runtime.h>
#include <cuda_fp16.h>
#include <cstdint>

// Problem constants
#define MB 8192      // B*S
#define HH 1024      // H
#define RR 2048      // R (= L)
#define SS 2048
#define BB 4
#define NCH 64       // scan chunks
#define CH  32       // steps per chunk

// fp32 scratch: scan chunk arrays only
__device__ float g_scratch[3ull * BB * NCH * RR];

// fp16 scratch: xh | wh(6 proj W) | wrod | rohp | 6 activation slabs
#define XH_OFF   0ull
#define WH_OFF   ((size_t)MB * HH)
#define WROD_OFF (WH_OFF + 6ull * RR * HH)
#define ROHP_OFF (WROD_OFF + (size_t)HH * 2 * RR)
#define ACT_OFF  (ROHP_OFF + (size_t)MB * 2 * RR)
__device__ __half g_half[ACT_OFF + 6ull * MB * RR];

// ---------------------------------------------------------------------------
// fp16 mma.sync m16n8k16 GEMM.  CTA 128x128, BK=32, 8 warps @ 64x32.
// smem tile [128][32] halves; 16B-chunk swizzle: chunk' = chunk ^ f(row),
// f(row) = (row&3) ^ ((row>>2)&1). Fragments via ldmatrix.x4.
// ---------------------------------------------------------------------------
#define BM 128
#define BN 128
#define BK 32
#define TILE_HALVES (128 * 32)     // 8KB per operand stage
#define TILE_BYTES  (TILE_HALVES * 2)

__device__ __forceinline__ uint32_t cvta_smem(const void* p) {
    uint32_t a;
    asm("{ .reg .u64 t; cvta.to.shared.u64 t, %1; cvt.u32.u64 %0, t; }"
        : "=r"(a) : "l"(p));
    return a;
}
__device__ __forceinline__ void ldsm_x4(uint32_t& r0, uint32_t& r1,
                                        uint32_t& r2, uint32_t& r3, uint32_t addr) {
    asm volatile("ldmatrix.sync.aligned.m8n8.x4.shared.b16 {%0,%1,%2,%3}, [%4];"
                 : "=r"(r0), "=r"(r1), "=r"(r2), "=r"(r3) : "r"(addr));
}
__device__ __forceinline__ void mma_f16(float c[4], const uint32_t a[4], const uint32_t b[2]) {
    asm volatile(
        "mma.sync.aligned.m16n8k16.row.col.f32.f16.f16.f32 "
        "{%0,%1,%2,%3}, {%4,%5,%6,%7}, {%8,%9}, {%0,%1,%2,%3};"
        : "+f"(c[0]), "+f"(c[1]), "+f"(c[2]), "+f"(c[3])
        : "r"(a[0]), "r"(a[1]), "r"(a[2]), "r"(a[3]), "r"(b[0]), "r"(b[1]));
}

__device__ __forceinline__ float act_apply(float x, int act) {
    if (act == 1) return tanhf(x);
    if (act == 2) return 1.0f / (1.0f + __expf(-x));
    if (act == 3) return x / (1.0f + __expf(-x));
    return x;
}

// acc += A[bm:+128, :K] @ W[bn:+128, :K]^T   (fp16 row-major, ld = K)
__device__ __forceinline__ void gemm_core(
    const __half* __restrict__ A, const __half* __restrict__ W, int K,
    int bm, int bn, __half* smA, __half* smB, int tid, float acc[4][4][4])
{
    const int lane = tid & 31;
    const int wid  = tid >> 5;
    const int wm   = (wid >> 2) * 64;   // 0 or 64
    const int wn   = (wid & 3) * 32;    // 0,32,64,96

    // ldmatrix per-lane geometry (A quads and B quads)
    const int arow  = ((lane >> 3) & 1) * 8 + (lane & 7);   // 0..15
    const int himat = lane >> 4;                            // 0/1: k-chunk select
    const int fa    = (arow & 3) ^ ((arow >> 2) & 1);
    const int bo    = ((lane >> 4) << 3) + (lane & 7);      // 0..15
    const int bchi  = (lane >> 3) & 1;
    const int fb    = (bo & 3) ^ ((bo >> 2) & 1);

    const uint32_t smA_u = cvta_smem(smA);
    const uint32_t smB_u = cvta_smem(smB);
    // lane base byte addresses (row*64 bytes)
    const uint32_t aLane = smA_u + (uint32_t)(wm + arow) * 64;
    const uint32_t bLane = smB_u + (uint32_t)(wn + bo) * 64;
    // per-kgroup swizzled chunk offsets (bytes)
    const uint32_t axor0 = (uint32_t)(((0 + himat) ^ fa) << 4);
    const uint32_t axor1 = (uint32_t)(((2 + himat) ^ fa) << 4);
    const uint32_t bxor0 = (uint32_t)(((0 + bchi) ^ fb) << 4);
    const uint32_t bxor1 = (uint32_t)(((2 + bchi) ^ fb) << 4);

    const int nk = K >> 5;
    uint4 sa[2], sb[2];

#define LDG_TILE(k0)                                                            \
    {                                                                           \
        _Pragma("unroll")                                                       \
        for (int i = 0; i < 2; ++i) {                                           \
            const int cid = tid + (i << 8);                                     \
            const int row = cid >> 2, ch = cid & 3;                             \
            sa[i] = *(const uint4*)(A + (size_t)(bm + row) * K + (k0) + (ch << 3)); \
            sb[i] = *(const uint4*)(W + (size_t)(bn + row) * K + (k0) + (ch << 3)); \
        }                                                                       \
    }

#define STS_TILE(buf)                                                           \
    {                                                                           \
        __half* a_ = smA + (buf) * TILE_HALVES;                                 \
        __half* b_ = smB + (buf) * TILE_HALVES;                                 \
        _Pragma("unroll")                                                       \
        for (int i = 0; i < 2; ++i) {                                           \
            const int cid = tid + (i << 8);                                     \
            const int row = cid >> 2, ch = cid & 3;                             \
            const int chs = ch ^ ((row & 3) ^ ((row >> 2) & 1));                \
            *(uint4*)(a_ + (row << 5) + (chs << 3)) = sa[i];                    \
            *(uint4*)(b_ + (row << 5) + (chs << 3)) = sb[i];                    \
        }                                                                       \
    }

#define FRAG_MMA(abase, bbase, ax, bx)                                          \
    {                                                                           \
        uint32_t af[4][4];                                                      \
        _Pragma("unroll")                                                       \
        for (int ms = 0; ms < 4; ++ms)                                          \
            ldsm_x4(af[ms][0], af[ms][1], af[ms][2], af[ms][3],                 \
                    (abase) + (uint32_t)(ms << 10) + (ax));                     \
        uint32_t bf[4][2];                                                      \
        _Pragma("unroll")                                                       \
        for (int np = 0; np < 2; ++np)                                          \
            ldsm_x4(bf[2*np][0], bf[2*np][1], bf[2*np+1][0], bf[2*np+1][1],     \
                    (bbase) + (uint32_t)(np << 10) + (bx));                     \
        _Pragma("unroll")                                                       \
        for (int ms = 0; ms < 4; ++ms)                                          \
            _Pragma("unroll")                                                   \
            for (int ns = 0; ns < 4; ++ns)                                      \
                mma_f16(acc[ms][ns], af[ms], bf[ns]);                           \
    }

    LDG_TILE(0);
    STS_TILE(0);
    __syncthreads();

    for (int kt = 0; kt < nk; ++kt) {
        const int buf = kt & 1;
        const uint32_t aB = aLane + (uint32_t)(buf * TILE_BYTES);
        const uint32_t bB = bLane + (uint32_t)(buf * TILE_BYTES);

        const bool more = (kt + 1 < nk);
        if (more) LDG_TILE((kt + 1) << 5);

        FRAG_MMA(aB, bB, axor0, bxor0);
        FRAG_MMA(aB, bB, axor1, bxor1);

        if (more) STS_TILE(buf ^ 1);
        __syncthreads();
    }
#undef LDG_TILE
#undef STS_TILE
#undef FRAG_MMA
}

// fp16 epilogue (activations)
__device__ __forceinline__ void epilogue_h(
    __half* __restrict__ O, int ldn, int bm, int bn, int tid,
    float acc[4][4][4], int act)
{
    const int lane = tid & 31;
    const int wid  = tid >> 5;
    const int wm   = (wid >> 2) * 64;
    const int wn   = (wid & 3) * 32;
    const int fr   = lane >> 2;
    const int fc   = lane & 3;

#pragma unroll
    for (int ms = 0; ms < 4; ++ms) {
#pragma unroll
        for (int ns = 0; ns < 4; ++ns) {
            const int m0 = bm + wm + ms * 16 + fr;
            const int n0 = bn + wn + ns * 8 + 2 * fc;
            __half2 h0 = __floats2half2_rn(act_apply(acc[ms][ns][0], act),
                                           act_apply(acc[ms][ns][1], act));
            __half2 h1 = __floats2half2_rn(act_apply(acc[ms][ns][2], act),
                                           act_apply(acc[ms][ns][3], act));
            *(__half2*)&O[(size_t)m0 * ldn + n0] = h0;
            *(__half2*)&O[(size_t)(m0 + 8) * ldn + n0] = h1;
        }
    }
}

// fp32 epilogue (final output)
__device__ __forceinline__ void epilogue_f(
    float* __restrict__ O, int ldn, int bm, int bn, int tid, float acc[4][4][4])
{
    const int lane = tid & 31;
    const int wid  = tid >> 5;
    const int wm   = (wid >> 2) * 64;
    const int wn   = (wid & 3) * 32;
    const int fr   = lane >> 2;
    const int fc   = lane & 3;

#pragma unroll
    for (int ms = 0; ms < 4; ++ms) {
#pragma unroll
        for (int ns = 0; ns < 4; ++ns) {
            const int m0 = bm + wm + ms * 16 + fr;
            const int n0 = bn + wn + ns * 8 + 2 * fc;
            float2 v0 = {acc[ms][ns][0], acc[ms][ns][1]};
            float2 v1 = {acc[ms][ns][2], acc[ms][ns][3]};
            *(float2*)&O[(size_t)m0 * ldn + n0] = v0;
            *(float2*)&O[(size_t)(m0 + 8) * ldn + n0] = v1;
        }
    }
}

// Fused 6-projection: grid (M/128=64, RR/128=16, 6), fp16 outputs
__global__ __launch_bounds__(256, 2)
void proj_tc(const __half* __restrict__ xh, const __half* __restrict__ wh,
             __half* __restrict__ acts)
{
    __shared__ __half smA[2 * TILE_HALVES];
    __shared__ __half smB[2 * TILE_HALVES];

    const int tid = threadIdx.x;
    const int bm = blockIdx.x * BM;
    const int bn = blockIdx.y * BN;
    const int z  = blockIdx.z;

    const __half* W = wh + (size_t)z * RR * HH;
    __half* O = acts + (size_t)z * MB * RR;
    // act: 0:f->tanh 1:g->sigmoid 2:c->silu 3:q 4:up 5:gate->silu
    const int act = (z == 0) ? 1 : (z == 1) ? 2 : (z == 2 || z == 5) ? 3 : 0;

    float acc[4][4][4];
#pragma unroll
    for (int i = 0; i < 4; ++i)
#pragma unroll
        for (int j = 0; j < 4; ++j)
#pragma unroll
            for (int k = 0; k < 4; ++k) acc[i][j][k] = 0.0f;

    gemm_core(xh, W, HH, bm, bn, smA, smB, tid, acc);
    epilogue_h(O, RR, bm, bn, tid, acc, act);
}

// Output GEMM: out[MB,HH] = rohp[MB,4096] @ wrod[HH,4096]^T.  grid (64, 8)
__global__ __launch_bounds__(256, 2)
void out_tc(const __half* __restrict__ rohp, const __half* __restrict__ wrod,
            float* __restrict__ O)
{
    __shared__ __half smA[2 * TILE_HALVES];
    __shared__ __half smB[2 * TILE_HALVES];

    const int tid = threadIdx.x;
    const int bm = blockIdx.x * BM;
    const int bn = blockIdx.y * BN;

    float acc[4][4][4];
#pragma unroll
    for (int i = 0; i < 4; ++i)
#pragma unroll
        for (int j = 0; j < 4; ++j)
#pragma unroll
            for (int k = 0; k < 4; ++k) acc[i][j][k] = 0.0f;

    gemm_core(rohp, wrod, 2 * RR, bm, bn, smA, smB, tid, acc);
    epilogue_f(O, HH, bm, bn, tid, acc);
}

// ---------------------------------------------------------------------------
// Conversions
// ---------------------------------------------------------------------------
__global__ void cvt_x(const float* __restrict__ src, __half* __restrict__ dst, int n4)
{
    const int i = blockIdx.x * blockDim.x + threadIdx.x;
    if (i < n4) {
        const float4 v = ((const float4*)src)[i];
        ((__half2*)dst)[2 * i]     = __floats2half2_rn(v.x, v.y);
        ((__half2*)dst)[2 * i + 1] = __floats2half2_rn(v.z, v.w);
    }
}

// 8 weights: z=0..5 -> wh slabs; z=6: Wro -> wrod[:,0:2048]; z=7: Wd -> wrod[:,2048:]
__global__ void cvt_w(const float* __restrict__ W0, const float* __restrict__ W1,
                      const float* __restrict__ W2, const float* __restrict__ W3,
                      const float* __restrict__ W4, const float* __restrict__ W5,
                      const float* __restrict__ Wro, const float* __restrict__ Wd,
                      __half* __restrict__ wh, __half* __restrict__ wrod)
{
    const int z = blockIdx.y;
    const int i = blockIdx.x * blockDim.x + threadIdx.x;   // float4 index < 512K
    const float* src;
    switch (z) {
        case 0: src = W0; break; case 1: src = W1; break;
        case 2: src = W2; break; case 3: src = W3; break;
        case 4: src = W4; break; case 5: src = W5; break;
        case 6: src = Wro; break; default: src = Wd; break;
    }
    const float4 v = ((const float4*)src)[i];
    const __half2 h0 = __floats2half2_rn(v.x, v.y);
    const __half2 h1 = __floats2half2_rn(v.z, v.w);

    __half* d;
    if (z < 6) {
        d = wh + (size_t)z * RR * HH + (size_t)i * 4;
    } else {
        const int row = i >> 9;            // / (RR/4 = 512)
        const int c4  = i & 511;
        d = wrod + (size_t)row * (2 * RR) + (z == 7 ? RR : 0) + (size_t)c4 * 4;
    }
    *(__half2*)d = h0;
    *(__half2*)(d + 2) = h1;
}

// ---------------------------------------------------------------------------
// Chunked parallel scan (fp16 inputs, fp32 arithmetic)
// ---------------------------------------------------------------------------
__global__ void scan_p1(const __half* __restrict__ F, const __half* __restrict__ G,
                        const __half* __restrict__ C,
                        float* __restrict__ chA, float* __restrict__ chY)
{
    const int t  = blockIdx.x * blockDim.x + threadIdx.x;
    const int r  = t & (RR - 1);
    const int bc = t >> 11;
    const int ch = bc & (NCH - 1);
    const int b  = bc >> 6;

    const size_t base = ((size_t)b * SS + (size_t)ch * CH) * RR + r;
    float a = 1.0f, y = 0.0f;
#pragma unroll 8
    for (int s = 0; s < CH; ++s) {
        const size_t idx = base + (size_t)s * RR;
        const float f  = __half2float(F[idx]);
        const float gc = __half2float(G[idx]) * __half2float(C[idx]);
        y = fmaf(f, y, gc);
        a *= f;
    }
    const int o = (b * NCH + ch) * RR + r;
    chA[o] = a;
    chY[o] = y;
}

__global__ void scan_p2(const float* __restrict__ chA, const float* __restrict__ chY,
                        const float* __restrict__ s0, float* __restrict__ carry)
{
    const int t = blockIdx.x * blockDim.x + threadIdx.x;
    const int r = t & (RR - 1);
    const int b = t >> 11;

    float c = s0[r];
#pragma unroll
    for (int ch = 0; ch < NCH; ++ch) {
        const int o = (b * NCH + ch) * RR + r;
        carry[o] = c;
        c = fmaf(chA[o], c, chY[o]);
    }
}

// phase 3: recompute states; RO = silu(q*state) fp16 -> rohp[:, 0:2048]
__global__ void scan_p3(const __half* __restrict__ F, const __half* __restrict__ G,
                        const __half* __restrict__ C, const __half* __restrict__ Q,
                        const float* __restrict__ carry, __half* __restrict__ rohp)
{
    const int t  = blockIdx.x * blockDim.x + threadIdx.x;
    const int r  = t & (RR - 1);
    const int bc = t >> 11;
    const int ch = bc & (NCH - 1);
    const int b  = bc >> 6;

    const size_t base = ((size_t)b * SS + (size_t)ch * CH) * RR + r;
    const size_t mrow0 = (size_t)b * SS + (size_t)ch * CH;
    float state = carry[(b * NCH + ch) * RR + r];
#pragma unroll 8
    for (int s = 0; s < CH; ++s) {
        const size_t idx = base + (size_t)s * RR;
        const float f  = __half2float(F[idx]);
        const float gc = __half2float(G[idx]) * __half2float(C[idx]);
        state = fmaf(f, state, gc);
        const float xq = __half2float(Q[idx]) * state;
        rohp[(mrow0 + s) * (2 * RR) + r] = __float2half(xq / (1.0f + __expf(-xq)));
    }
}

// hp = up * gate (gate already silu'd) fp16 -> rohp[:, 2048:4096]
__global__ void mul_h(const __half* __restrict__ up, const __half* __restrict__ gate,
                      __half* __restrict__ rohp, int n8)
{
    const int i = blockIdx.x * blockDim.x + threadIdx.x;   // 8 halves per thread
    if (i < n8) {
        const uint4 u4 = ((const uint4*)up)[i];
        const uint4 g4 = ((const uint4*)gate)[i];
        const __half2* uh = (const __half2*)&u4;
        const __half2* gh = (const __half2*)&g4;
        uint4 o4;
        __half2* oh = (__half2*)&o4;
#pragma unroll
        for (int j = 0; j < 4; ++j) {
            const float2 uf = __half22float2(uh[j]);
            const float2 gf = __half22float2(gh[j]);
            oh[j] = __floats2half2_rn(uf.x * gf.x, uf.y * gf.y);
        }
        const int row = i >> 8;            // / (RR/8 = 256)
        const int c8  = i & 255;
        *(uint4*)(rohp + (size_t)row * (2 * RR) + RR + (size_t)c8 * 8) = o4;
    }
}

// ---------------------------------------------------------------------------
extern "C" void kernel_launch(void* const* d_in, const int* in_sizes, int n_in,
                              void* d_out, int out_size)
{
    const float* x   = (const float*)d_in[0];
    const float* Wf  = (const float*)d_in[1];
    const float* Wi  = (const float*)d_in[2];
    const float* Wv  = (const float*)d_in[3];
    const float* Wq  = (const float*)d_in[4];
    const float* Wro = (const float*)d_in[5];
    const float* Wu  = (const float*)d_in[6];
    const float* Wg  = (const float*)d_in[7];
    const float* Wd  = (const float*)d_in[8];
    const float* s0  = (const float*)d_in[9];
    float* out = (float*)d_out;

    float* scr = nullptr;
    cudaGetSymbolAddress((void**)&scr, g_scratch);
    __half* hscr = nullptr;
    cudaGetSymbolAddress((void**)&hscr, g_half);

    float* chA = scr;
    float* chY = chA + (size_t)BB * NCH * RR;
    float* car = chY + (size_t)BB * NCH * RR;

    __half* xh   = hscr + XH_OFF;
    __half* wh   = hscr + WH_OFF;
    __half* wrod = hscr + WROD_OFF;
    __half* rohp = hscr + ROHP_OFF;
    __half* acts = hscr + ACT_OFF;
    __half* f  = acts + 0ull * MB * RR;
    __half* g  = acts + 1ull * MB * RR;
    __half* c  = acts + 2ull * MB * RR;
    __half* q  = acts + 3ull * MB * RR;
    __half* up = acts + 4ull * MB * RR;
    __half* gt = acts + 5ull * MB * RR;

    // 0. fp32 -> fp16
    cvt_x<<<(MB * HH / 4) / 256, 256>>>(x, xh, MB * HH / 4);
    cvt_w<<<dim3((RR * HH / 4) / 256, 8), 256>>>(Wf, Wi, Wv, Wq, Wu, Wg, Wro, Wd, wh, wrod);

    // 1. six projections (fp16 tensor cores, ldmatrix fragments)
    proj_tc<<<dim3(MB / BM, RR / BN, 6), 256>>>(xh, wh, acts);

    // 2. chunked scan; p3 writes RO fp16 into rohp[:, 0:2048]
    scan_p1<<<(BB * NCH * RR) / 256, 256>>>(f, g, c, chA, chY);
    scan_p2<<<(BB * RR) / 256, 256>>>(chA, chY, s0, car);
    scan_p3<<<(BB * NCH * RR) / 256, 256>>>(f, g, c, q, car, rohp);

    // 3. hp = up*gate fp16 into rohp[:, 2048:4096]
    mul_h<<<(MB * RR / 8) / 256, 256>>>(up, gt, rohp, MB * RR / 8);

    // 4. out = rohp @ wrod^T  (K = 4096, rec + local in one GEMM)
    out_tc<<<dim3(MB / BM, HH / BN), 256>>>(rohp, wrod, out);
}